// round 1
// baseline (speedup 1.0000x reference)
#include <cuda_runtime.h>
#include <cuda_bf16.h>
#include <cstdint>

// Problem constants (fixed by the reference)
#define N_NODES 50000
#define D_FEAT  128
#define N_EDGES 800000

// Scratch: tangent-space features (25.6 MB) as a device global (no alloc allowed)
__device__ float g_tangent[(size_t)N_NODES * D_FEAT];

// ---------------------------------------------------------------------------
// Kernel 1: logmap0 — one warp per row. Each lane owns one float4 (4 of 128).
// factor = artanh(clip(||x||)) / max(||x||, 1e-15)   (c = 1)
// ---------------------------------------------------------------------------
__global__ __launch_bounds__(256) void tangent_kernel(const float* __restrict__ x) {
    int gw   = (blockIdx.x * blockDim.x + threadIdx.x) >> 5;   // global warp = row
    int lane = threadIdx.x & 31;
    if (gw >= N_NODES) return;

    const float4* xr = reinterpret_cast<const float4*>(x) + (size_t)gw * 32;
    float4 v = xr[lane];

    float ss = v.x * v.x + v.y * v.y + v.z * v.z + v.w * v.w;
    #pragma unroll
    for (int o = 16; o > 0; o >>= 1)
        ss += __shfl_xor_sync(0xFFFFFFFFu, ss, o);

    float norm = sqrtf(ss);
    norm = fmaxf(norm, 1e-15f);
    // clip artanh argument strictly below 1 (never active for this data: ||x|| ~ 0.01)
    float u = fminf(norm, 0.99999988f);   // largest float < 1
    float factor = atanhf(u) / norm;

    v.x *= factor; v.y *= factor; v.z *= factor; v.w *= factor;
    float4* tr = reinterpret_cast<float4*>(g_tangent) + (size_t)gw * 32;
    tr[lane] = v;
}

// ---------------------------------------------------------------------------
// Kernel 2: edge scatter — one warp per edge. Each lane gathers one float4 of
// the source row, scales by the edge value, and vector-reduces (red.v4.f32)
// into the destination row. out and g_tangent both fit in L2.
// ---------------------------------------------------------------------------
__global__ __launch_bounds__(256) void edge_kernel(
    const int*   __restrict__ adj_rows,
    const int*   __restrict__ adj_cols,
    const float* __restrict__ adj_vals,
    float*       __restrict__ out)
{
    int gw   = (blockIdx.x * blockDim.x + threadIdx.x) >> 5;   // global warp = edge
    int lane = threadIdx.x & 31;
    if (gw >= N_EDGES) return;

    int   row = adj_rows[gw];
    int   col = adj_cols[gw];
    float val = adj_vals[gw];

    const float4* src = reinterpret_cast<const float4*>(g_tangent) + (size_t)col * 32;
    float4 t = src[lane];
    float a = val * t.x, b = val * t.y, c = val * t.z, d = val * t.w;

    float* dst = out + (size_t)row * D_FEAT + lane * 4;
    asm volatile("red.global.add.v4.f32 [%0], {%1, %2, %3, %4};"
                 :: "l"(dst), "f"(a), "f"(b), "f"(c), "f"(d)
                 : "memory");
}

// ---------------------------------------------------------------------------
// Launch: tangent -> zero out -> scatter (default stream, graph-capturable)
// Inputs (metadata order): x [N*D f32], adj_rows [E i32], adj_cols [E i32],
// adj_vals [E f32]. Output: [N*D f32].
// ---------------------------------------------------------------------------
extern "C" void kernel_launch(void* const* d_in, const int* in_sizes, int n_in,
                              void* d_out, int out_size) {
    const float* x        = (const float*)d_in[0];
    const int*   adj_rows = (const int*)  d_in[1];
    const int*   adj_cols = (const int*)  d_in[2];
    const float* adj_vals = (const float*)d_in[3];
    float*       out      = (float*)      d_out;

    // 1) tangent-space map: one warp per row
    {
        int warps_per_block = 256 / 32;
        int blocks = (N_NODES + warps_per_block - 1) / warps_per_block;
        tangent_kernel<<<blocks, 256>>>(x);
    }

    // 2) zero the output (poisoned by harness)
    cudaMemsetAsync(d_out, 0, (size_t)out_size * sizeof(float));

    // 3) edge scatter: one warp per edge
    {
        int warps_per_block = 256 / 32;
        int blocks = (N_EDGES + warps_per_block - 1) / warps_per_block;
        edge_kernel<<<blocks, 256>>>(adj_rows, adj_cols, adj_vals, out);
    }
}

// round 2
// speedup vs baseline: 1.5612x; 1.5612x over previous
#include <cuda_runtime.h>
#include <cuda_bf16.h>
#include <cstdint>

#define N_NODES 50000
#define D_FEAT  128
#define N_EDGES 800000
#define CAP     64          // per-row bucket capacity (max observed degree ~40)
#define OVF_CAP 4096

// Scratch (device globals; no allocation allowed)
__device__ float              g_tangent[(size_t)N_NODES * D_FEAT];     // 25.6 MB
__device__ unsigned long long g_bucket[(size_t)N_NODES * CAP];         // 25.6 MB: (col<<32)|val_bits
__device__ int                g_cnt[N_NODES];
__device__ int                g_ovf_cnt;
__device__ uint4              g_ovf[OVF_CAP];                           // {row, col, val_bits, _}

// ---------------------------------------------------------------------------
// Kernel 0: zero the per-row counters + overflow counter
// ---------------------------------------------------------------------------
__global__ void zero_kernel() {
    int i = blockIdx.x * blockDim.x + threadIdx.x;
    if (i < N_NODES) g_cnt[i] = 0;
    if (i == 0) g_ovf_cnt = 0;
}

// ---------------------------------------------------------------------------
// Kernel 1: logmap0 — one warp per row (c = 1)
// ---------------------------------------------------------------------------
__global__ __launch_bounds__(256) void tangent_kernel(const float* __restrict__ x) {
    int gw   = (blockIdx.x * blockDim.x + threadIdx.x) >> 5;
    int lane = threadIdx.x & 31;
    if (gw >= N_NODES) return;

    const float4* xr = reinterpret_cast<const float4*>(x) + (size_t)gw * 32;
    float4 v = xr[lane];

    float ss = v.x * v.x + v.y * v.y + v.z * v.z + v.w * v.w;
    #pragma unroll
    for (int o = 16; o > 0; o >>= 1)
        ss += __shfl_xor_sync(0xFFFFFFFFu, ss, o);

    float norm = fmaxf(sqrtf(ss), 1e-15f);
    float u = fminf(norm, 0.99999988f);          // artanh clamp (inactive for this data)
    float factor = atanhf(u) / norm;

    v.x *= factor; v.y *= factor; v.z *= factor; v.w *= factor;
    reinterpret_cast<float4*>(g_tangent)[(size_t)gw * 32 + lane] = v;
}

// ---------------------------------------------------------------------------
// Kernel 2: bucket edges by destination row (thread per edge).
// atomic cursor doubles as the degree count.
// ---------------------------------------------------------------------------
__global__ __launch_bounds__(256) void scatter_kernel(
    const int* __restrict__ adj_rows,
    const int* __restrict__ adj_cols,
    const float* __restrict__ adj_vals)
{
    int e = blockIdx.x * blockDim.x + threadIdx.x;
    if (e >= N_EDGES) return;
    int   r = adj_rows[e];
    int   c = adj_cols[e];
    float v = adj_vals[e];

    int pos = atomicAdd(&g_cnt[r], 1);
    if (pos < CAP) {
        g_bucket[(size_t)r * CAP + pos] =
            ((unsigned long long)(unsigned)c << 32) | (unsigned)__float_as_uint(v);
    } else {
        int o = atomicAdd(&g_ovf_cnt, 1);
        if (o < OVF_CAP) g_ovf[o] = make_uint4((unsigned)r, (unsigned)c, __float_as_uint(v), 0u);
    }
}

// ---------------------------------------------------------------------------
// Kernel 3: aggregate — one warp per node. Register accumulation, single store.
// Unrolled by 2 for gather MLP.
// ---------------------------------------------------------------------------
__global__ __launch_bounds__(256) void aggregate_kernel(float* __restrict__ out) {
    int gw   = (blockIdx.x * blockDim.x + threadIdx.x) >> 5;
    int lane = threadIdx.x & 31;
    if (gw >= N_NODES) return;

    int n = g_cnt[gw];
    n = (n < CAP) ? n : CAP;
    const unsigned long long* bk = g_bucket + (size_t)gw * CAP;
    const float4* tang = reinterpret_cast<const float4*>(g_tangent);

    float ax = 0.f, ay = 0.f, az = 0.f, aw = 0.f;
    int e = 0;
    for (; e + 2 <= n; e += 2) {
        unsigned long long p0 = bk[e];
        unsigned long long p1 = bk[e + 1];
        int   c0 = (int)(p0 >> 32);
        int   c1 = (int)(p1 >> 32);
        float v0 = __uint_as_float((unsigned)p0);
        float v1 = __uint_as_float((unsigned)p1);
        float4 t0 = tang[(size_t)c0 * 32 + lane];
        float4 t1 = tang[(size_t)c1 * 32 + lane];
        ax += v0 * t0.x; ay += v0 * t0.y; az += v0 * t0.z; aw += v0 * t0.w;
        ax += v1 * t1.x; ay += v1 * t1.y; az += v1 * t1.z; aw += v1 * t1.w;
    }
    if (e < n) {
        unsigned long long p0 = bk[e];
        int   c0 = (int)(p0 >> 32);
        float v0 = __uint_as_float((unsigned)p0);
        float4 t0 = tang[(size_t)c0 * 32 + lane];
        ax += v0 * t0.x; ay += v0 * t0.y; az += v0 * t0.z; aw += v0 * t0.w;
    }

    reinterpret_cast<float4*>(out)[(size_t)gw * 32 + lane] = make_float4(ax, ay, az, aw);
}

// ---------------------------------------------------------------------------
// Kernel 4: overflow fixup (normally 0 iterations). red.v4 into out.
// ---------------------------------------------------------------------------
__global__ __launch_bounds__(256) void overflow_kernel(float* __restrict__ out) {
    int n = g_ovf_cnt;
    n = (n < OVF_CAP) ? n : OVF_CAP;
    int lane = threadIdx.x & 31;
    int warps = (gridDim.x * blockDim.x) >> 5;
    for (int i = (blockIdx.x * blockDim.x + threadIdx.x) >> 5; i < n; i += warps) {
        uint4 q = g_ovf[i];
        float v = __uint_as_float(q.z);
        float4 t = reinterpret_cast<const float4*>(g_tangent)[(size_t)q.y * 32 + lane];
        float a = v * t.x, b = v * t.y, c = v * t.z, d = v * t.w;
        float* dst = out + (size_t)q.x * D_FEAT + lane * 4;
        asm volatile("red.global.add.v4.f32 [%0], {%1, %2, %3, %4};"
                     :: "l"(dst), "f"(a), "f"(b), "f"(c), "f"(d)
                     : "memory");
    }
}

// ---------------------------------------------------------------------------
// Launch sequence (default stream, graph-capturable, allocation-free)
// ---------------------------------------------------------------------------
extern "C" void kernel_launch(void* const* d_in, const int* in_sizes, int n_in,
                              void* d_out, int out_size) {
    const float* x        = (const float*)d_in[0];
    const int*   adj_rows = (const int*)  d_in[1];
    const int*   adj_cols = (const int*)  d_in[2];
    const float* adj_vals = (const float*)d_in[3];
    float*       out      = (float*)      d_out;

    zero_kernel<<<(N_NODES + 255) / 256, 256>>>();

    {
        int blocks = (N_NODES * 32 + 255) / 256;
        tangent_kernel<<<blocks, 256>>>(x);
    }

    scatter_kernel<<<(N_EDGES + 255) / 256, 256>>>(adj_rows, adj_cols, adj_vals);

    {
        int blocks = (N_NODES * 32 + 255) / 256;
        aggregate_kernel<<<blocks, 256>>>(out);
    }

    overflow_kernel<<<8, 256>>>(out);
}

// round 3
// speedup vs baseline: 1.8227x; 1.1675x over previous
#include <cuda_runtime.h>
#include <cuda_bf16.h>
#include <cstdint>

#define N_NODES 50000
#define D_FEAT  128
#define N_EDGES 800000
#define CAP     64          // per-row bucket capacity (max observed degree ~40)
#define OVF_CAP 4096

// Scratch (device globals; no allocation allowed)
__device__ float              g_factor[N_NODES];                  // 200 KB: artanh(|x|)/|x|
__device__ unsigned long long g_bucket[(size_t)N_NODES * CAP];    // 25.6 MB: (col<<32)|scale_bits
__device__ int                g_cnt[N_NODES];
__device__ int                g_ovf_cnt;
__device__ uint4              g_ovf[OVF_CAP];                     // {row, col, scale_bits, _}

// ---------------------------------------------------------------------------
// Kernel A: per-row logmap0 factor + zero counters. One warp per row.
// ---------------------------------------------------------------------------
__global__ __launch_bounds__(256) void factor_kernel(const float* __restrict__ x) {
    int gw   = (blockIdx.x * blockDim.x + threadIdx.x) >> 5;
    int lane = threadIdx.x & 31;
    if (gw >= N_NODES) return;

    const float4* xr = reinterpret_cast<const float4*>(x) + (size_t)gw * 32;
    float4 v = xr[lane];

    float ss = v.x * v.x + v.y * v.y + v.z * v.z + v.w * v.w;
    #pragma unroll
    for (int o = 16; o > 0; o >>= 1)
        ss += __shfl_xor_sync(0xFFFFFFFFu, ss, o);

    if (lane == 0) {
        float norm = fmaxf(sqrtf(ss), 1e-15f);
        float u = fminf(norm, 0.99999988f);      // artanh clamp (inactive: ||x|| ~ 0.01)
        g_factor[gw] = atanhf(u) / norm;
        g_cnt[gw] = 0;
        if (gw == 0) g_ovf_cnt = 0;
    }
}

// ---------------------------------------------------------------------------
// Kernel B: bucket edges by destination row; pre-fold factor into the weight.
// ---------------------------------------------------------------------------
__global__ __launch_bounds__(256) void scatter_kernel(
    const int* __restrict__ adj_rows,
    const int* __restrict__ adj_cols,
    const float* __restrict__ adj_vals)
{
    int e = blockIdx.x * blockDim.x + threadIdx.x;
    if (e >= N_EDGES) return;
    int   r = adj_rows[e];
    int   c = adj_cols[e];
    float s = adj_vals[e] * g_factor[c];

    int pos = atomicAdd(&g_cnt[r], 1);
    if (pos < CAP) {
        g_bucket[(size_t)r * CAP + pos] =
            ((unsigned long long)(unsigned)c << 32) | (unsigned)__float_as_uint(s);
    } else {
        int o = atomicAdd(&g_ovf_cnt, 1);
        if (o < OVF_CAP) g_ovf[o] = make_uint4((unsigned)r, (unsigned)c, __float_as_uint(s), 0u);
    }
}

// ---------------------------------------------------------------------------
// Kernel C: aggregate — one warp per node, register accumulation, unroll x4.
// Gathers raw x (factor already folded into edge scale). Overflow handled
// in-kernel by scanning the (normally empty) overflow list.
// ---------------------------------------------------------------------------
__global__ __launch_bounds__(256) void aggregate_kernel(
    const float* __restrict__ x, float* __restrict__ out)
{
    int gw   = (blockIdx.x * blockDim.x + threadIdx.x) >> 5;
    int lane = threadIdx.x & 31;
    if (gw >= N_NODES) return;

    int raw_n = g_cnt[gw];
    int n = (raw_n < CAP) ? raw_n : CAP;
    const unsigned long long* bk = g_bucket + (size_t)gw * CAP;
    const float4* xv = reinterpret_cast<const float4*>(x);

    float ax = 0.f, ay = 0.f, az = 0.f, aw = 0.f;
    int e = 0;
    for (; e + 4 <= n; e += 4) {
        unsigned long long p0 = bk[e];
        unsigned long long p1 = bk[e + 1];
        unsigned long long p2 = bk[e + 2];
        unsigned long long p3 = bk[e + 3];
        float4 t0 = xv[(size_t)(p0 >> 32) * 32 + lane];
        float4 t1 = xv[(size_t)(p1 >> 32) * 32 + lane];
        float4 t2 = xv[(size_t)(p2 >> 32) * 32 + lane];
        float4 t3 = xv[(size_t)(p3 >> 32) * 32 + lane];
        float s0 = __uint_as_float((unsigned)p0);
        float s1 = __uint_as_float((unsigned)p1);
        float s2 = __uint_as_float((unsigned)p2);
        float s3 = __uint_as_float((unsigned)p3);
        ax += s0 * t0.x; ay += s0 * t0.y; az += s0 * t0.z; aw += s0 * t0.w;
        ax += s1 * t1.x; ay += s1 * t1.y; az += s1 * t1.z; aw += s1 * t1.w;
        ax += s2 * t2.x; ay += s2 * t2.y; az += s2 * t2.z; aw += s2 * t2.w;
        ax += s3 * t3.x; ay += s3 * t3.y; az += s3 * t3.z; aw += s3 * t3.w;
    }
    for (; e < n; e++) {
        unsigned long long p0 = bk[e];
        float4 t0 = xv[(size_t)(p0 >> 32) * 32 + lane];
        float s0 = __uint_as_float((unsigned)p0);
        ax += s0 * t0.x; ay += s0 * t0.y; az += s0 * t0.z; aw += s0 * t0.w;
    }

    // Overflow fixup (rare path; normally raw_n <= CAP for every row)
    if (raw_n > CAP) {
        int ovf_n = g_ovf_cnt;
        ovf_n = (ovf_n < OVF_CAP) ? ovf_n : OVF_CAP;
        for (int i = 0; i < ovf_n; i++) {
            uint4 q = g_ovf[i];
            if ((int)q.x == gw) {
                float s = __uint_as_float(q.z);
                float4 t = xv[(size_t)q.y * 32 + lane];
                ax += s * t.x; ay += s * t.y; az += s * t.z; aw += s * t.w;
            }
        }
    }

    reinterpret_cast<float4*>(out)[(size_t)gw * 32 + lane] = make_float4(ax, ay, az, aw);
}

// ---------------------------------------------------------------------------
// Launch sequence: factor+zero -> scatter -> aggregate (3 kernels)
// ---------------------------------------------------------------------------
extern "C" void kernel_launch(void* const* d_in, const int* in_sizes, int n_in,
                              void* d_out, int out_size) {
    const float* x        = (const float*)d_in[0];
    const int*   adj_rows = (const int*)  d_in[1];
    const int*   adj_cols = (const int*)  d_in[2];
    const float* adj_vals = (const float*)d_in[3];
    float*       out      = (float*)      d_out;

    {
        int blocks = (N_NODES * 32 + 255) / 256;
        factor_kernel<<<blocks, 256>>>(x);
    }
    scatter_kernel<<<(N_EDGES + 255) / 256, 256>>>(adj_rows, adj_cols, adj_vals);
    {
        int blocks = (N_NODES * 32 + 255) / 256;
        aggregate_kernel<<<blocks, 256>>>(x, out);
    }
}

// round 4
// speedup vs baseline: 1.9906x; 1.0921x over previous
#include <cuda_runtime.h>
#include <cuda_fp16.h>
#include <cstdint>

#define N_NODES 50000
#define D_FEAT  128
#define N_EDGES 800000
#define CAP     64          // per-row bucket capacity (max observed degree ~40)
#define OVF_CAP 4096

// Scratch (device globals; no allocation allowed)
__device__ __half             g_xh[(size_t)N_NODES * D_FEAT];     // 12.8 MB: fp16 tangent
__device__ unsigned long long g_bucket[(size_t)N_NODES * CAP];    // (col<<32)|val_bits
__device__ int                g_cnt[N_NODES];
__device__ int                g_ovf_cnt;
__device__ uint4              g_ovf[OVF_CAP];                     // {row, col, val_bits, _}

// ---------------------------------------------------------------------------
// Kernel A: logmap0 factor + fp16 tangent convert + zero counters.
// 8 rows per warp, 4 lanes per row. Each lane: 8 independent LDG.128 (MLP=8),
// 2-shuffle group reduce, then converts its 32 elements to fp16.
// ---------------------------------------------------------------------------
__global__ __launch_bounds__(256) void factor_kernel(const float* __restrict__ x) {
    const int warp_id = (blockIdx.x * blockDim.x + threadIdx.x) >> 5;
    const int lane    = threadIdx.x & 31;
    const int l       = lane & 3;          // lane within row group [0,4)
    const int r_loc   = lane >> 2;         // row within warp [0,8)
    const int row     = warp_id * 8 + r_loc;

    // zero counters (50000 < 256 * blocks; thread-linear)
    int t = blockIdx.x * blockDim.x + threadIdx.x;
    if (t < N_NODES) g_cnt[t] = 0;
    if (t == 0) g_ovf_cnt = 0;

    if (row >= N_NODES) return;

    const float4* xr = reinterpret_cast<const float4*>(x) + (size_t)row * 32;
    float4 v[8];
    #pragma unroll
    for (int k = 0; k < 8; k++) v[k] = xr[l + 4 * k];

    float ss = 0.f;
    #pragma unroll
    for (int k = 0; k < 8; k++)
        ss += v[k].x * v[k].x + v[k].y * v[k].y + v[k].z * v[k].z + v[k].w * v[k].w;
    ss += __shfl_xor_sync(0xFFFFFFFFu, ss, 1);
    ss += __shfl_xor_sync(0xFFFFFFFFu, ss, 2);

    float norm = fmaxf(sqrtf(ss), 1e-15f);
    float u = fminf(norm, 0.99999988f);          // artanh clamp (inactive: ||x|| ~ 0.01)
    float factor = atanhf(u) / norm;

    uint2* xh = reinterpret_cast<uint2*>(g_xh + (size_t)row * D_FEAT);
    #pragma unroll
    for (int k = 0; k < 8; k++) {
        __half2 lo = __floats2half2_rn(v[k].x * factor, v[k].y * factor);
        __half2 hi = __floats2half2_rn(v[k].z * factor, v[k].w * factor);
        uint2 packed;
        packed.x = *reinterpret_cast<unsigned*>(&lo);
        packed.y = *reinterpret_cast<unsigned*>(&hi);
        xh[l + 4 * k] = packed;
    }
}

// ---------------------------------------------------------------------------
// Kernel B: bucket edges by destination row (raw edge weight; factor already
// baked into g_xh).
// ---------------------------------------------------------------------------
__global__ __launch_bounds__(256) void scatter_kernel(
    const int* __restrict__ adj_rows,
    const int* __restrict__ adj_cols,
    const float* __restrict__ adj_vals)
{
    int e = blockIdx.x * blockDim.x + threadIdx.x;
    if (e >= N_EDGES) return;
    int   r = adj_rows[e];
    int   c = adj_cols[e];
    float s = adj_vals[e];

    int pos = atomicAdd(&g_cnt[r], 1);
    if (pos < CAP) {
        g_bucket[(size_t)r * CAP + pos] =
            ((unsigned long long)(unsigned)c << 32) | (unsigned)__float_as_uint(s);
    } else {
        int o = atomicAdd(&g_ovf_cnt, 1);
        if (o < OVF_CAP) g_ovf[o] = make_uint4((unsigned)r, (unsigned)c, __float_as_uint(s), 0u);
    }
}

// ---------------------------------------------------------------------------
// Kernel C: aggregate — one warp per node. fp16 gathers (256B/edge), fp32
// register accumulation, unroll x4, single fp32 store.
// ---------------------------------------------------------------------------
__device__ __forceinline__ void acc_edge(float& ax, float& ay, float& az, float& aw,
                                         unsigned long long p, int lane) {
    const uint2* row = reinterpret_cast<const uint2*>(g_xh + (size_t)(p >> 32) * D_FEAT);
    uint2 q = row[lane];
    float s = __uint_as_float((unsigned)p);
    float2 lo = __half22float2(*reinterpret_cast<__half2*>(&q.x));
    float2 hi = __half22float2(*reinterpret_cast<__half2*>(&q.y));
    ax += s * lo.x; ay += s * lo.y; az += s * hi.x; aw += s * hi.y;
}

__global__ __launch_bounds__(256) void aggregate_kernel(float* __restrict__ out) {
    int gw   = (blockIdx.x * blockDim.x + threadIdx.x) >> 5;
    int lane = threadIdx.x & 31;
    if (gw >= N_NODES) return;

    int raw_n = g_cnt[gw];
    int n = (raw_n < CAP) ? raw_n : CAP;
    const unsigned long long* bk = g_bucket + (size_t)gw * CAP;

    float ax = 0.f, ay = 0.f, az = 0.f, aw = 0.f;
    int e = 0;
    for (; e + 4 <= n; e += 4) {
        unsigned long long p0 = bk[e];
        unsigned long long p1 = bk[e + 1];
        unsigned long long p2 = bk[e + 2];
        unsigned long long p3 = bk[e + 3];
        acc_edge(ax, ay, az, aw, p0, lane);
        acc_edge(ax, ay, az, aw, p1, lane);
        acc_edge(ax, ay, az, aw, p2, lane);
        acc_edge(ax, ay, az, aw, p3, lane);
    }
    for (; e < n; e++)
        acc_edge(ax, ay, az, aw, bk[e], lane);

    // Overflow fixup (rare path; normally raw_n <= CAP for every row)
    if (raw_n > CAP) {
        int ovf_n = g_ovf_cnt;
        ovf_n = (ovf_n < OVF_CAP) ? ovf_n : OVF_CAP;
        for (int i = 0; i < ovf_n; i++) {
            uint4 q = g_ovf[i];
            if ((int)q.x == gw) {
                unsigned long long p =
                    ((unsigned long long)q.y << 32) | (unsigned long long)q.z;
                acc_edge(ax, ay, az, aw, p, lane);
            }
        }
    }

    reinterpret_cast<float4*>(out)[(size_t)gw * 32 + lane] = make_float4(ax, ay, az, aw);
}

// ---------------------------------------------------------------------------
// Launch sequence: factor/convert+zero -> scatter -> aggregate
// ---------------------------------------------------------------------------
extern "C" void kernel_launch(void* const* d_in, const int* in_sizes, int n_in,
                              void* d_out, int out_size) {
    const float* x        = (const float*)d_in[0];
    const int*   adj_rows = (const int*)  d_in[1];
    const int*   adj_cols = (const int*)  d_in[2];
    const float* adj_vals = (const float*)d_in[3];
    float*       out      = (float*)      d_out;

    {
        // 8 rows per warp, 8 warps per block -> 64 rows per block
        int blocks = (N_NODES + 63) / 64;
        factor_kernel<<<blocks, 256>>>(x);
    }
    scatter_kernel<<<(N_EDGES + 255) / 256, 256>>>(adj_rows, adj_cols, adj_vals);
    {
        int blocks = (N_NODES * 32 + 255) / 256;
        aggregate_kernel<<<blocks, 256>>>(out);
    }
}